// round 7
// baseline (speedup 1.0000x reference)
#include <cuda_runtime.h>
#include <cuda_bf16.h>
#include <math.h>

// Problem shape (fixed by setup_inputs): N=50000, E=800000, D=256
#define DIM 256
#define MAXN 50000
#define MAXE 800000
#define SCAN_THREADS 1024

// Scratch (static __device__ globals — no runtime allocation allowed)
__device__ int   g_is64;                      // 1 if edge_index is int64
__device__ int   g_cnt[MAXN];                 // edge count per target node
__device__ int   g_start[MAXN + 1];           // CSR row starts
__device__ int   g_cursor[MAXN];              // placement cursors
__device__ int   g_esrc[MAXE];                // CSR: source node per slot
__device__ float g_dinv[MAXN];                // rsqrt(deg)
__device__ float g_h[(size_t)MAXN * DIM];     // h = x @ W
__device__ float g_colsum[DIM];               // column sums of sigmoid(...)

// ---------------------------------------------------------------------------
// k_detect: decide whether edge buffer is int64 or int32.
// int64 little-endian values < 2^31  =>  every odd 32-bit word is 0.
// Real int32 indices at odd positions are ~never all zero over 256 samples.
// ---------------------------------------------------------------------------
__global__ void k_detect(const int* __restrict__ p32, int nwords) {
    __shared__ int any_nonzero;
    if (threadIdx.x == 0) any_nonzero = 0;
    __syncthreads();
    int idx = 1 + 2 * threadIdx.x;           // odd words
    if (idx < nwords && p32[idx] != 0) atomicOr(&any_nonzero, 1);
    __syncthreads();
    if (threadIdx.x == 0) g_is64 = any_nonzero ? 0 : 1;
}

__device__ __forceinline__ int load_idx(const int* p32, long long pos,
                                        int stride, int N) {
    int v = p32[pos * stride];               // stride 1 (i32) or 2 (i64 low word)
    // defensive clamp — garbage must never reach an atomic address
    return min(max(v, 0), N - 1);
}

// ---------------------------------------------------------------------------
__global__ void k_init(int N) {
    int i = blockIdx.x * blockDim.x + threadIdx.x;
    if (i < N)   g_cnt[i] = 0;
    if (i < DIM) g_colsum[i] = 0.0f;
}

// ---------------------------------------------------------------------------
__global__ void k_hist(const int* __restrict__ p32, int E, int N) {
    int e = blockIdx.x * blockDim.x + threadIdx.x;
    if (e < E) {
        int stride = 1 + g_is64;
        int c = load_idx(p32, (long long)E + e, stride, N);
        atomicAdd(&g_cnt[c], 1);
    }
}

// ---------------------------------------------------------------------------
// k_scan: single-block exclusive prefix scan of g_cnt -> g_start/g_cursor.
// Also computes dinv = rsqrt(cnt + 1)  (+1 = self loop).
// ---------------------------------------------------------------------------
__global__ void k_scan(int N) {
    __shared__ int partial[SCAN_THREADS];
    const int t = threadIdx.x;
    const int chunk = (N + SCAN_THREADS - 1) / SCAN_THREADS;
    const int s = t * chunk;
    const int e = min(s + chunk, N);

    int sum = 0;
    for (int i = s; i < e; i++) sum += g_cnt[i];
    partial[t] = sum;
    __syncthreads();

    for (int off = 1; off < SCAN_THREADS; off <<= 1) {
        int v = (t >= off) ? partial[t - off] : 0;
        __syncthreads();
        partial[t] += v;
        __syncthreads();
    }

    int run = (t == 0) ? 0 : partial[t - 1];   // exclusive base for this chunk
    for (int i = s; i < e; i++) {
        int c = g_cnt[i];
        g_start[i]  = run;
        g_cursor[i] = run;
        g_dinv[i]   = rsqrtf((float)(c + 1));
        run += c;
    }
    if (t == SCAN_THREADS - 1) g_start[N] = run;   // == E
}

// ---------------------------------------------------------------------------
__global__ void k_place(const int* __restrict__ p32, int E, int N) {
    int e = blockIdx.x * blockDim.x + threadIdx.x;
    if (e < E) {
        int stride = 1 + g_is64;
        int r = load_idx(p32, (long long)e, stride, N);
        int c = load_idx(p32, (long long)E + e, stride, N);
        int pos = atomicAdd(&g_cursor[c], 1);
        if (pos < MAXE) g_esrc[pos] = r;
    }
}

// ---------------------------------------------------------------------------
// k_gemm: h = x @ W     x:[N,256] W:[256,256]
// Tile: BM=64, BN=64, BK=16. 256 threads as 16x16, each computes 4x4.
// Tile loads vectorized to LDG.128 (one float4 per thread per tile).
// ---------------------------------------------------------------------------
__global__ void k_gemm(const float* __restrict__ x,
                       const float* __restrict__ W, int N) {
    __shared__ float xs[64][17];
    __shared__ float ws[16][64];

    const int tx = threadIdx.x & 15;
    const int ty = threadIdx.x >> 4;
    const int rowBase = blockIdx.x * 64;
    const int colBase = blockIdx.y * 64;

    // vector-load thread maps
    const int xr  = threadIdx.x >> 2;        // 0..63 row in x tile
    const int xc4 = threadIdx.x & 3;         // 0..3  float4 within 16 cols
    const int wr  = threadIdx.x >> 4;        // 0..15 row in W tile
    const int wc4 = threadIdx.x & 15;        // 0..15 float4 within 64 cols

    float acc[4][4];
#pragma unroll
    for (int i = 0; i < 4; i++)
#pragma unroll
        for (int j = 0; j < 4; j++) acc[i][j] = 0.0f;

    for (int k0 = 0; k0 < DIM; k0 += 16) {
        // x tile 64x16: one float4 per thread
        {
            int gr = rowBase + xr;
            float4 v = (gr < N)
                ? *(const float4*)&x[(long long)gr * DIM + k0 + xc4 * 4]
                : make_float4(0.f, 0.f, 0.f, 0.f);
            xs[xr][xc4 * 4 + 0] = v.x;
            xs[xr][xc4 * 4 + 1] = v.y;
            xs[xr][xc4 * 4 + 2] = v.z;
            xs[xr][xc4 * 4 + 3] = v.w;
        }
        // W tile 16x64: one float4 per thread, vector store (ws unpadded)
        {
            float4 v = *(const float4*)&W[(long long)(k0 + wr) * DIM + colBase + wc4 * 4];
            *(float4*)&ws[wr][wc4 * 4] = v;
        }
        __syncthreads();

#pragma unroll
        for (int k = 0; k < 16; k++) {
            float a[4], b[4];
#pragma unroll
            for (int i = 0; i < 4; i++) a[i] = xs[ty * 4 + i][k];
#pragma unroll
            for (int j = 0; j < 4; j++) b[j] = ws[k][tx * 4 + j];
#pragma unroll
            for (int i = 0; i < 4; i++)
#pragma unroll
                for (int j = 0; j < 4; j++) acc[i][j] = fmaf(a[i], b[j], acc[i][j]);
        }
        __syncthreads();
    }

#pragma unroll
    for (int i = 0; i < 4; i++) {
        int gr = rowBase + ty * 4 + i;
        if (gr < N) {
            float4 v = make_float4(acc[i][0], acc[i][1], acc[i][2], acc[i][3]);
            *(float4*)&g_h[(long long)gr * DIM + colBase + tx * 4] = v;
        }
    }
}

// ---------------------------------------------------------------------------
// k_gather: fused aggregate + bias + sigmoid + column-sum.
// Warp per node (grid-stride). Lane owns cols [lane*4,+4) and [128+lane*4,+4).
// Edge loop 2x unrolled: both edge indices issued before the dependent
// h-row loads, doubling MLP on the L2-latency chain.
// ---------------------------------------------------------------------------
#define GATHER_BLOCKS 1184   // 148 SMs * 8
__device__ __forceinline__ float sigmoidf(float v) {
    return 1.0f / (1.0f + expf(-v));
}

__global__ void k_gather(const float* __restrict__ b_conv, int N) {
    const int lane = threadIdx.x & 31;
    const int wid  = threadIdx.x >> 5;
    const int gw   = blockIdx.x * 8 + wid;
    const int nwarps = gridDim.x * 8;
    const int d0 = lane * 4;
    const int d1 = 128 + lane * 4;

    const float4 bc0 = *(const float4*)&b_conv[d0];
    const float4 bc1 = *(const float4*)&b_conv[d1];

    float4 cs0 = make_float4(0.f, 0.f, 0.f, 0.f);
    float4 cs1 = make_float4(0.f, 0.f, 0.f, 0.f);

    for (int n = gw; n < N; n += nwarps) {
        const float dn = g_dinv[n];
        const int base = g_start[n];
        const int end  = g_start[n + 1];

        // self-loop contribution: norm = dinv[n]^2
        const float wn = dn * dn;
        float4 h0 = *(const float4*)&g_h[(size_t)n * DIM + d0];
        float4 h1 = *(const float4*)&g_h[(size_t)n * DIM + d1];
        float4 a0 = make_float4(h0.x * wn, h0.y * wn, h0.z * wn, h0.w * wn);
        float4 a1 = make_float4(h1.x * wn, h1.y * wn, h1.z * wn, h1.w * wn);

        int i = base;
        for (; i + 2 <= end; i += 2) {
            int ra = g_esrc[i];
            int rb = g_esrc[i + 1];
            float wa = g_dinv[ra] * dn;
            float wb = g_dinv[rb] * dn;
            float4 va0 = *(const float4*)&g_h[(size_t)ra * DIM + d0];
            float4 va1 = *(const float4*)&g_h[(size_t)ra * DIM + d1];
            float4 vb0 = *(const float4*)&g_h[(size_t)rb * DIM + d0];
            float4 vb1 = *(const float4*)&g_h[(size_t)rb * DIM + d1];
            a0.x = fmaf(va0.x, wa, a0.x); a0.y = fmaf(va0.y, wa, a0.y);
            a0.z = fmaf(va0.z, wa, a0.z); a0.w = fmaf(va0.w, wa, a0.w);
            a1.x = fmaf(va1.x, wa, a1.x); a1.y = fmaf(va1.y, wa, a1.y);
            a1.z = fmaf(va1.z, wa, a1.z); a1.w = fmaf(va1.w, wa, a1.w);
            a0.x = fmaf(vb0.x, wb, a0.x); a0.y = fmaf(vb0.y, wb, a0.y);
            a0.z = fmaf(vb0.z, wb, a0.z); a0.w = fmaf(vb0.w, wb, a0.w);
            a1.x = fmaf(vb1.x, wb, a1.x); a1.y = fmaf(vb1.y, wb, a1.y);
            a1.z = fmaf(vb1.z, wb, a1.z); a1.w = fmaf(vb1.w, wb, a1.w);
        }
        if (i < end) {
            int   r  = g_esrc[i];
            float we = g_dinv[r] * dn;
            float4 v0 = *(const float4*)&g_h[(size_t)r * DIM + d0];
            float4 v1 = *(const float4*)&g_h[(size_t)r * DIM + d1];
            a0.x = fmaf(v0.x, we, a0.x); a0.y = fmaf(v0.y, we, a0.y);
            a0.z = fmaf(v0.z, we, a0.z); a0.w = fmaf(v0.w, we, a0.w);
            a1.x = fmaf(v1.x, we, a1.x); a1.y = fmaf(v1.y, we, a1.y);
            a1.z = fmaf(v1.z, we, a1.z); a1.w = fmaf(v1.w, we, a1.w);
        }

        cs0.x += sigmoidf(a0.x + bc0.x);
        cs0.y += sigmoidf(a0.y + bc0.y);
        cs0.z += sigmoidf(a0.z + bc0.z);
        cs0.w += sigmoidf(a0.w + bc0.w);
        cs1.x += sigmoidf(a1.x + bc1.x);
        cs1.y += sigmoidf(a1.y + bc1.y);
        cs1.z += sigmoidf(a1.z + bc1.z);
        cs1.w += sigmoidf(a1.w + bc1.w);
    }

    // block-level reduction: smem atomics, then one global atomic per column
    __shared__ float scol[DIM];
    scol[threadIdx.x] = 0.0f;
    __syncthreads();
    atomicAdd(&scol[d0 + 0], cs0.x);
    atomicAdd(&scol[d0 + 1], cs0.y);
    atomicAdd(&scol[d0 + 2], cs0.z);
    atomicAdd(&scol[d0 + 3], cs0.w);
    atomicAdd(&scol[d1 + 0], cs1.x);
    atomicAdd(&scol[d1 + 1], cs1.y);
    atomicAdd(&scol[d1 + 2], cs1.z);
    atomicAdd(&scol[d1 + 3], cs1.w);
    __syncthreads();
    atomicAdd(&g_colsum[threadIdx.x], scol[threadIdx.x]);
}

// ---------------------------------------------------------------------------
__global__ void k_final(const float* __restrict__ w_lin,
                        const float* __restrict__ b_lin,
                        float* __restrict__ out, int N) {
    __shared__ float red[DIM];
    int d = threadIdx.x;
    red[d] = g_colsum[d] * (1.0f / (float)N) * w_lin[d];
    __syncthreads();
    for (int s = 128; s > 0; s >>= 1) {
        if (d < s) red[d] += red[d + s];
        __syncthreads();
    }
    if (d == 0) {
        float z = red[0] + b_lin[0];
        out[0] = 1.0f / (1.0f + expf(-z));
    }
}

// ---------------------------------------------------------------------------
extern "C" void kernel_launch(void* const* d_in, const int* in_sizes, int n_in,
                              void* d_out, int out_size) {
    const float* x      = (const float*)d_in[0];
    const int*   e32    = (const int*)d_in[1];     // edge_index, dtype detected
    const float* W      = (const float*)d_in[2];
    const float* b_conv = (const float*)d_in[3];
    const float* w_lin  = (const float*)d_in[4];
    const float* b_lin  = (const float*)d_in[5];
    float*       out    = (float*)d_out;

    int N = in_sizes[0] / DIM;
    int E = in_sizes[1] / 2;   // element count of edge_index is 2*E either way

    // detect int32 vs int64 layout (odd 32-bit words all zero => int64)
    k_detect<<<1, 256>>>(e32, 2 * E);

    k_init<<<(N + 255) / 256, 256>>>(N);
    k_hist<<<(E + 255) / 256, 256>>>(e32, E, N);
    k_scan<<<1, SCAN_THREADS>>>(N);
    k_place<<<(E + 255) / 256, 256>>>(e32, E, N);
    {
        dim3 grid((N + 63) / 64, DIM / 64);
        k_gemm<<<grid, 256>>>(x, W, N);
    }
    k_gather<<<GATHER_BLOCKS, 256>>>(b_conv, N);
    k_final<<<1, 256>>>(w_lin, b_lin, out, N);
}

// round 12
// speedup vs baseline: 2.2740x; 2.2740x over previous
#include <cuda_runtime.h>
#include <cuda_bf16.h>
#include <math.h>

// Problem shape (fixed by setup_inputs): N=50000, E=800000, D=256
#define DIM 256
#define MAXN 50000
#define MAXE 800000

// Parallel scan config
#define SCAN_CHUNK 512
#define NUM_SCAN_BLOCKS ((MAXN + SCAN_CHUNK - 1) / SCAN_CHUNK)   // 98

// Scratch (static __device__ globals — no runtime allocation allowed)
__device__ int   g_is64;
__device__ int   g_cnt[MAXN];
__device__ int   g_start[MAXN + 1];
__device__ int   g_cursor[MAXN];
__device__ int   g_esrc[MAXE];
__device__ float g_dinv[MAXN];
__device__ float g_h[(size_t)MAXN * DIM];
__device__ float g_colsum[DIM];
__device__ int   g_blocksum[NUM_SCAN_BLOCKS];
__device__ int   g_blockbase[NUM_SCAN_BLOCKS];

// ---------------------------------------------------------------------------
// k_detect: int64 vs int32 edge buffer (odd 32-bit words all zero => int64)
// ---------------------------------------------------------------------------
__global__ void k_detect(const int* __restrict__ p32, int nwords) {
    __shared__ int any_nonzero;
    if (threadIdx.x == 0) any_nonzero = 0;
    __syncthreads();
    int idx = 1 + 2 * threadIdx.x;
    if (idx < nwords && p32[idx] != 0) atomicOr(&any_nonzero, 1);
    __syncthreads();
    if (threadIdx.x == 0) g_is64 = any_nonzero ? 0 : 1;
}

__device__ __forceinline__ int load_idx(const int* p32, long long pos,
                                        int stride, int N) {
    int v = p32[pos * stride];
    return min(max(v, 0), N - 1);   // clamp: garbage must never reach an atomic
}

// ---------------------------------------------------------------------------
__global__ void k_init(int N) {
    int i = blockIdx.x * blockDim.x + threadIdx.x;
    if (i < N)   g_cnt[i] = 0;
    if (i < DIM) g_colsum[i] = 0.0f;
}

// ---------------------------------------------------------------------------
__global__ void k_hist(const int* __restrict__ p32, int E, int N) {
    int e = blockIdx.x * blockDim.x + threadIdx.x;
    if (e < E) {
        int stride = 1 + g_is64;
        int c = load_idx(p32, (long long)E + e, stride, N);
        atomicAdd(&g_cnt[c], 1);
    }
}

// ---------------------------------------------------------------------------
// 3-phase parallel scan (replaces measured 110us serial single-block scan)
// ---------------------------------------------------------------------------
__global__ void k_scan1(int N) {
    __shared__ int wsum[8];
    const int b = blockIdx.x, t = threadIdx.x;
    const int i0 = b * SCAN_CHUNK + 2 * t;
    const int i1 = i0 + 1;
    int e0 = (i0 < N) ? g_cnt[i0] : 0;
    int e1 = (i1 < N) ? g_cnt[i1] : 0;
    int s = e0 + e1;
#pragma unroll
    for (int o = 16; o > 0; o >>= 1) s += __shfl_down_sync(0xffffffffu, s, o);
    if ((t & 31) == 0) wsum[t >> 5] = s;
    __syncthreads();
    if (t < 8) {
        int v = wsum[t];
#pragma unroll
        for (int o = 4; o > 0; o >>= 1) v += __shfl_down_sync(0xffu, v, o);
        if (t == 0) g_blocksum[b] = v;
    }
}

__global__ void k_scan2() {
    __shared__ int sh[128];
    const int t = threadIdx.x;
    int v = (t < NUM_SCAN_BLOCKS) ? g_blocksum[t] : 0;
    sh[t] = v;
    __syncthreads();
    for (int o = 1; o < 128; o <<= 1) {
        int u = (t >= o) ? sh[t - o] : 0;
        __syncthreads();
        sh[t] += u;
        __syncthreads();
    }
    if (t < NUM_SCAN_BLOCKS) g_blockbase[t] = sh[t] - v;  // exclusive
}

__global__ void k_scan3(int N) {
    __shared__ int warp_inc[8];
    const int b = blockIdx.x, t = threadIdx.x;
    const int lane = t & 31, wid = t >> 5;
    const int i0 = b * SCAN_CHUNK + 2 * t;
    const int i1 = i0 + 1;
    int e0 = (i0 < N) ? g_cnt[i0] : 0;
    int e1 = (i1 < N) ? g_cnt[i1] : 0;
    int s = e0 + e1;

    int v = s;
#pragma unroll
    for (int o = 1; o < 32; o <<= 1) {
        int u = __shfl_up_sync(0xffffffffu, v, o);
        if (lane >= o) v += u;
    }
    if (lane == 31) warp_inc[wid] = v;
    __syncthreads();
    if (t < 8) {
        int w = warp_inc[t];
#pragma unroll
        for (int o = 1; o < 8; o <<= 1) {
            int u = __shfl_up_sync(0xffu, w, o);
            if (t >= o) w += u;
        }
        warp_inc[t] = w;
    }
    __syncthreads();

    int base = g_blockbase[b] + (wid > 0 ? warp_inc[wid - 1] : 0) + (v - s);
    if (i0 < N) {
        g_start[i0]  = base;
        g_cursor[i0] = base;
        g_dinv[i0]   = rsqrtf((float)(e0 + 1));
        if (i0 == N - 1) g_start[N] = base + e0;
    }
    if (i1 < N) {
        int b1 = base + e0;
        g_start[i1]  = b1;
        g_cursor[i1] = b1;
        g_dinv[i1]   = rsqrtf((float)(e1 + 1));
        if (i1 == N - 1) g_start[N] = b1 + e1;
    }
}

// ---------------------------------------------------------------------------
__global__ void k_place(const int* __restrict__ p32, int E, int N) {
    int e = blockIdx.x * blockDim.x + threadIdx.x;
    if (e < E) {
        int stride = 1 + g_is64;
        int r = load_idx(p32, (long long)e, stride, N);
        int c = load_idx(p32, (long long)E + e, stride, N);
        int pos = atomicAdd(&g_cursor[c], 1);
        if (pos < MAXE) g_esrc[pos] = r;
    }
}

// ---------------------------------------------------------------------------
// k_gemm: h = x @ W via tf32 tensor cores (mma.sync m16n8k8).
// Block tile 128x64, BK=32, 8 warps as 4(M)x2(N), warp tile 32x32 = 2x4 mmas.
// Smem pads (36 / 72 floats) make fragment LDS lane-bijective (conflict-free).
// ---------------------------------------------------------------------------
#define BM 128
#define BN 64
#define BK 32

__device__ __forceinline__ unsigned f2tf32(float f) {
    unsigned r;
    asm("cvt.rna.tf32.f32 %0, %1;" : "=r"(r) : "f"(f));
    return r;
}

__device__ __forceinline__ void mma_tf32(float* d, const unsigned* a,
                                         const unsigned* b) {
    asm volatile(
        "mma.sync.aligned.m16n8k8.row.col.f32.tf32.tf32.f32 "
        "{%0,%1,%2,%3}, {%4,%5,%6,%7}, {%8,%9}, {%0,%1,%2,%3};"
        : "+f"(d[0]), "+f"(d[1]), "+f"(d[2]), "+f"(d[3])
        : "r"(a[0]), "r"(a[1]), "r"(a[2]), "r"(a[3]), "r"(b[0]), "r"(b[1]));
}

__global__ void k_gemm(const float* __restrict__ x,
                       const float* __restrict__ W, int N) {
    __shared__ float xs[BM][36];   // 128x32, row stride 36 (4g+t bijective)
    __shared__ float ws[BK][72];   // 32x64, row stride 72 (8t+g bijective)

    const int tid  = threadIdx.x;
    const int warp = tid >> 5;
    const int lane = tid & 31;
    const int g    = lane >> 2;    // fragment group 0..7
    const int t4   = lane & 3;     // fragment thread-in-group 0..3

    const int rowBase = blockIdx.x * BM;
    const int colBase = blockIdx.y * BN;
    const int wm = (warp >> 1) * 32;   // warp M offset within block tile
    const int wn = (warp & 1) * 32;    // warp N offset

    float acc[2][4][4];
#pragma unroll
    for (int m = 0; m < 2; m++)
#pragma unroll
        for (int n = 0; n < 4; n++)
#pragma unroll
            for (int r = 0; r < 4; r++) acc[m][n][r] = 0.0f;

    for (int kc = 0; kc < DIM; kc += BK) {
        // load x tile 128x32: 4 float4 per thread
#pragma unroll
        for (int l = 0; l < 4; l++) {
            int idx = tid + l * 256;
            int r = idx >> 3, c4 = idx & 7;
            int gr = rowBase + r;
            float4 v = (gr < N)
                ? *(const float4*)&x[(size_t)gr * DIM + kc + c4 * 4]
                : make_float4(0.f, 0.f, 0.f, 0.f);
            *(float4*)&xs[r][c4 * 4] = v;
        }
        // load W tile 32x64: 2 float4 per thread
#pragma unroll
        for (int l = 0; l < 2; l++) {
            int idx = tid + l * 256;
            int r = idx >> 4, c4 = idx & 15;
            float4 v = *(const float4*)&W[(size_t)(kc + r) * DIM + colBase + c4 * 4];
            *(float4*)&ws[r][c4 * 4] = v;
        }
        __syncthreads();

#pragma unroll
        for (int ks = 0; ks < BK; ks += 8) {
            unsigned A[2][4], B[4][2];
#pragma unroll
            for (int m = 0; m < 2; m++) {
                int r0 = wm + m * 16 + g;
                A[m][0] = f2tf32(xs[r0][ks + t4]);
                A[m][1] = f2tf32(xs[r0 + 8][ks + t4]);
                A[m][2] = f2tf32(xs[r0][ks + t4 + 4]);
                A[m][3] = f2tf32(xs[r0 + 8][ks + t4 + 4]);
            }
#pragma unroll
            for (int n = 0; n < 4; n++) {
                int c = wn + n * 8 + g;
                B[n][0] = f2tf32(ws[ks + t4][c]);
                B[n][1] = f2tf32(ws[ks + t4 + 4][c]);
            }
#pragma unroll
            for (int m = 0; m < 2; m++)
#pragma unroll
                for (int n = 0; n < 4; n++) mma_tf32(acc[m][n], A[m], B[n]);
        }
        __syncthreads();
    }

    // store: D tile 16x8 per mma; c0,c1 at (g, 2t),(g, 2t+1); c2,c3 at (g+8, .)
#pragma unroll
    for (int m = 0; m < 2; m++) {
        int r0 = rowBase + wm + m * 16 + g;
        int r1 = r0 + 8;
#pragma unroll
        for (int n = 0; n < 4; n++) {
            int c = colBase + wn + n * 8 + 2 * t4;
            if (r0 < N)
                *(float2*)&g_h[(size_t)r0 * DIM + c] =
                    make_float2(acc[m][n][0], acc[m][n][1]);
            if (r1 < N)
                *(float2*)&g_h[(size_t)r1 * DIM + c] =
                    make_float2(acc[m][n][2], acc[m][n][3]);
        }
    }
}

// ---------------------------------------------------------------------------
// k_gather: fused aggregate + bias + sigmoid + column-sum. Warp per node.
// ---------------------------------------------------------------------------
#define GATHER_BLOCKS 1184
__device__ __forceinline__ float sigmoidf(float v) {
    return 1.0f / (1.0f + expf(-v));
}

__global__ void k_gather(const float* __restrict__ b_conv, int N) {
    const int lane = threadIdx.x & 31;
    const int wid  = threadIdx.x >> 5;
    const int gw   = blockIdx.x * 8 + wid;
    const int nwarps = gridDim.x * 8;
    const int d0 = lane * 4;
    const int d1 = 128 + lane * 4;

    const float4 bc0 = *(const float4*)&b_conv[d0];
    const float4 bc1 = *(const float4*)&b_conv[d1];

    float4 cs0 = make_float4(0.f, 0.f, 0.f, 0.f);
    float4 cs1 = make_float4(0.f, 0.f, 0.f, 0.f);

    for (int n = gw; n < N; n += nwarps) {
        const float dn = g_dinv[n];
        const int base = g_start[n];
        const int end  = g_start[n + 1];

        const float wn = dn * dn;   // self-loop norm
        float4 h0 = *(const float4*)&g_h[(size_t)n * DIM + d0];
        float4 h1 = *(const float4*)&g_h[(size_t)n * DIM + d1];
        float4 a0 = make_float4(h0.x * wn, h0.y * wn, h0.z * wn, h0.w * wn);
        float4 a1 = make_float4(h1.x * wn, h1.y * wn, h1.z * wn, h1.w * wn);

        int i = base;
        for (; i + 2 <= end; i += 2) {
            int ra = g_esrc[i];
            int rb = g_esrc[i + 1];
            float wa = g_dinv[ra] * dn;
            float wb = g_dinv[rb] * dn;
            float4 va0 = *(const float4*)&g_h[(size_t)ra * DIM + d0];
            float4 va1 = *(const float4*)&g_h[(size_t)ra * DIM + d1];
            float4 vb0 = *(const float4*)&g_h[(size_t)rb * DIM + d0];
            float4 vb1 = *(const float4*)&g_h[(size_t)rb * DIM + d1];
            a0.x = fmaf(va0.x, wa, a0.x); a0.y = fmaf(va0.y, wa, a0.y);
            a0.z = fmaf(va0.z, wa, a0.z); a0.w = fmaf(va0.w, wa, a0.w);
            a1.x = fmaf(va1.x, wa, a1.x); a1.y = fmaf(va1.y, wa, a1.y);
            a1.z = fmaf(va1.z, wa, a1.z); a1.w = fmaf(va1.w, wa, a1.w);
            a0.x = fmaf(vb0.x, wb, a0.x); a0.y = fmaf(vb0.y, wb, a0.y);
            a0.z = fmaf(vb0.z, wb, a0.z); a0.w = fmaf(vb0.w, wb, a0.w);
            a1.x = fmaf(vb1.x, wb, a1.x); a1.y = fmaf(vb1.y, wb, a1.y);
            a1.z = fmaf(vb1.z, wb, a1.z); a1.w = fmaf(vb1.w, wb, a1.w);
        }
        if (i < end) {
            int   r  = g_esrc[i];
            float we = g_dinv[r] * dn;
            float4 v0 = *(const float4*)&g_h[(size_t)r * DIM + d0];
            float4 v1 = *(const float4*)&g_h[(size_t)r * DIM + d1];
            a0.x = fmaf(v0.x, we, a0.x); a0.y = fmaf(v0.y, we, a0.y);
            a0.z = fmaf(v0.z, we, a0.z); a0.w = fmaf(v0.w, we, a0.w);
            a1.x = fmaf(v1.x, we, a1.x); a1.y = fmaf(v1.y, we, a1.y);
            a1.z = fmaf(v1.z, we, a1.z); a1.w = fmaf(v1.w, we, a1.w);
        }

        cs0.x += sigmoidf(a0.x + bc0.x);
        cs0.y += sigmoidf(a0.y + bc0.y);
        cs0.z += sigmoidf(a0.z + bc0.z);
        cs0.w += sigmoidf(a0.w + bc0.w);
        cs1.x += sigmoidf(a1.x + bc1.x);
        cs1.y += sigmoidf(a1.y + bc1.y);
        cs1.z += sigmoidf(a1.z + bc1.z);
        cs1.w += sigmoidf(a1.w + bc1.w);
    }

    __shared__ float scol[DIM];
    scol[threadIdx.x] = 0.0f;
    __syncthreads();
    atomicAdd(&scol[d0 + 0], cs0.x);
    atomicAdd(&scol[d0 + 1], cs0.y);
    atomicAdd(&scol[d0 + 2], cs0.z);
    atomicAdd(&scol[d0 + 3], cs0.w);
    atomicAdd(&scol[d1 + 0], cs1.x);
    atomicAdd(&scol[d1 + 1], cs1.y);
    atomicAdd(&scol[d1 + 2], cs1.z);
    atomicAdd(&scol[d1 + 3], cs1.w);
    __syncthreads();
    atomicAdd(&g_colsum[threadIdx.x], scol[threadIdx.x]);
}

// ---------------------------------------------------------------------------
__global__ void k_final(const float* __restrict__ w_lin,
                        const float* __restrict__ b_lin,
                        float* __restrict__ out, int N) {
    __shared__ float red[DIM];
    int d = threadIdx.x;
    red[d] = g_colsum[d] * (1.0f / (float)N) * w_lin[d];
    __syncthreads();
    for (int s = 128; s > 0; s >>= 1) {
        if (d < s) red[d] += red[d + s];
        __syncthreads();
    }
    if (d == 0) {
        float z = red[0] + b_lin[0];
        out[0] = 1.0f / (1.0f + expf(-z));
    }
}

// ---------------------------------------------------------------------------
extern "C" void kernel_launch(void* const* d_in, const int* in_sizes, int n_in,
                              void* d_out, int out_size) {
    const float* x      = (const float*)d_in[0];
    const int*   e32    = (const int*)d_in[1];
    const float* W      = (const float*)d_in[2];
    const float* b_conv = (const float*)d_in[3];
    const float* w_lin  = (const float*)d_in[4];
    const float* b_lin  = (const float*)d_in[5];
    float*       out    = (float*)d_out;

    int N = in_sizes[0] / DIM;
    int E = in_sizes[1] / 2;

    k_detect<<<1, 256>>>(e32, 2 * E);
    k_init<<<(N + 255) / 256, 256>>>(N);
    k_hist<<<(E + 255) / 256, 256>>>(e32, E, N);

    k_scan1<<<NUM_SCAN_BLOCKS, 256>>>(N);
    k_scan2<<<1, 128>>>();
    k_scan3<<<NUM_SCAN_BLOCKS, 256>>>(N);

    k_place<<<(E + 255) / 256, 256>>>(e32, E, N);
    {
        dim3 grid((N + BM - 1) / BM, DIM / BN);
        k_gemm<<<grid, 256>>>(x, W, N);
    }
    k_gather<<<GATHER_BLOCKS, 256>>>(b_conv, N);
    k_final<<<1, 256>>>(w_lin, b_lin, out, N);
}